// round 1
// baseline (speedup 1.0000x reference)
#include <cuda_runtime.h>

#define DIN  128
#define DOUT 128
#define EDIM 16
#define MAXN 50176
#define BN_EPS 1e-5f

// ---------------- device scratch (static; no runtime allocation) ------------
__device__ float g_x  [MAXN * DOUT];   // feats @ W_rel^T + b_rel
__device__ float g_res[MAXN * DOUT];   // relu(feats @ W_res^T + b_res)
__device__ float g_xs [MAXN * DOUT];   // scatter-add of x[src] per dst
__device__ float g_ea [MAXN * EDIM];   // scatter-add of edge_attr per dst
__device__ float g_deg[MAXN];          // float degree per dst
__device__ float g_h  [MAXN * DOUT];   // pre-BN activations
__device__ float g_sum  [DOUT];
__device__ float g_sumsq[DOUT];
__device__ float g_scale[DOUT];
__device__ float g_shift[DOUT];
__device__ int   g_is64;               // edge_index dtype flag

// ---------------- helpers ----------------------------------------------------
__device__ __forceinline__ void red_add_v4(float* p, float4 v) {
    asm volatile("red.global.add.v4.f32 [%0], {%1,%2,%3,%4};"
                 :: "l"(p), "f"(v.x), "f"(v.y), "f"(v.z), "f"(v.w)
                 : "memory");
}

// ---------------- K0: detect edge_index dtype (int64 vs int32) --------------
// Indices are < N < 2^31. If stored as int64 (little endian) every odd 32-bit
// word is 0. If int32, odd words are random indices (P(all zero) ~ 0).
__global__ void k0_detect(const unsigned int* __restrict__ ei_words) {
    __shared__ int any_nz;
    if (threadIdx.x == 0) any_nz = 0;
    __syncthreads();
    int nz = 0;
    for (int i = threadIdx.x; i < 1024; i += blockDim.x)
        nz |= (ei_words[2 * i + 1] != 0u);
    if (nz) atomicOr(&any_nz, 1);
    __syncthreads();
    if (threadIdx.x == 0) g_is64 = any_nz ? 0 : 1;
}

// ---------------- K1: fused node GEMMs + scratch zeroing --------------------
// Block tile: 64 nodes x 256 output cols (cols 0..127 -> W_rel, 128..255 -> W_res)
// 256 threads, each computes an 8x8 register tile. K tiled by 32 through smem.
__global__ __launch_bounds__(256, 2)
void k1_node_gemm(const float* __restrict__ feats,
                  const float* __restrict__ Wrel, const float* __restrict__ brel,
                  const float* __restrict__ Wres, const float* __restrict__ bres,
                  int N)
{
    __shared__ float fs[32 * 68];    // [k][node] pitch 68
    __shared__ float ws[32 * 260];   // [k][ocol] pitch 260

    const int tid = threadIdx.x;
    const int m0  = blockIdx.x * 64;

    // zero per-node scatter scratch for this block's nodes
    for (int i = tid; i < 64 * DOUT; i += 256) {
        int n = m0 + (i >> 7);
        if (n < N) g_xs[n * DOUT + (i & 127)] = 0.f;
    }
    for (int i = tid; i < 64 * EDIM; i += 256) {
        int n = m0 + (i >> 4);
        if (n < N) g_ea[n * EDIM + (i & 15)] = 0.f;
    }
    if (tid < 64 && m0 + tid < N) g_deg[m0 + tid] = 0.f;
    if (blockIdx.x == 0 && tid < DOUT) { g_sum[tid] = 0.f; g_sumsq[tid] = 0.f; }

    const int o8 = (tid >> 3) * 8;   // output col base (0..248)
    const int n8 = (tid & 7) * 8;    // node base within tile (0..56)

    float acc[8][8];
    #pragma unroll
    for (int oi = 0; oi < 8; oi++) {
        int c = o8 + oi;
        float b = (c < DOUT) ? brel[c] : bres[c - DOUT];
        #pragma unroll
        for (int nj = 0; nj < 8; nj++) acc[oi][nj] = b;
    }

    for (int t = 0; t < DIN / 32; t++) {
        __syncthreads();
        // load feats tile transposed: fs[k][n]
        for (int i = tid; i < 64 * 32; i += 256) {
            int kk = i & 31, n = i >> 5;
            int node = m0 + n;
            fs[kk * 68 + n] = (node < N) ? feats[node * DIN + t * 32 + kk] : 0.f;
        }
        // load weight tile transposed: ws[k][o], concat [W_rel ; W_res]
        for (int i = tid; i < 256 * 32; i += 256) {
            int kk = i & 31, o = i >> 5;
            float v = (o < DOUT) ? Wrel[o * DIN + t * 32 + kk]
                                 : Wres[(o - DOUT) * DIN + t * 32 + kk];
            ws[kk * 260 + o] = v;
        }
        __syncthreads();

        #pragma unroll
        for (int kk = 0; kk < 32; kk++) {
            float4 w0 = *(const float4*)&ws[kk * 260 + o8];
            float4 w1 = *(const float4*)&ws[kk * 260 + o8 + 4];
            float4 f0 = *(const float4*)&fs[kk * 68 + n8];
            float4 f1 = *(const float4*)&fs[kk * 68 + n8 + 4];
            float wv[8] = {w0.x, w0.y, w0.z, w0.w, w1.x, w1.y, w1.z, w1.w};
            float fv[8] = {f0.x, f0.y, f0.z, f0.w, f1.x, f1.y, f1.z, f1.w};
            #pragma unroll
            for (int oi = 0; oi < 8; oi++)
                #pragma unroll
                for (int nj = 0; nj < 8; nj++)
                    acc[oi][nj] += wv[oi] * fv[nj];
        }
    }

    // store: cols <128 -> g_x (no relu), cols >=128 -> g_res (relu applied)
    #pragma unroll
    for (int nj = 0; nj < 8; nj++) {
        int node = m0 + n8 + nj;
        if (node >= N) continue;
        #pragma unroll
        for (int oi = 0; oi < 8; oi += 4) {
            int c = o8 + oi;
            float4 v = make_float4(acc[oi][nj], acc[oi+1][nj], acc[oi+2][nj], acc[oi+3][nj]);
            if (c < DOUT) {
                *(float4*)&g_x[node * DOUT + c] = v;
            } else {
                v.x = fmaxf(v.x, 0.f); v.y = fmaxf(v.y, 0.f);
                v.z = fmaxf(v.z, 0.f); v.w = fmaxf(v.w, 0.f);
                *(float4*)&g_res[node * DOUT + (c - DOUT)] = v;
            }
        }
    }
}

// ---------------- K2: per-edge gather + scatter-add --------------------------
// One warp per edge: gather x[src] (512B coalesced), red.v4 into g_xs[dst];
// lanes 0-3 scatter the 16-float edge_attr, lane 4 bumps degree.
__global__ __launch_bounds__(256)
void k2_edge(const void* __restrict__ ei_raw, const float* __restrict__ eattr, int E)
{
    int w = (blockIdx.x * blockDim.x + threadIdx.x) >> 5;
    int lane = threadIdx.x & 31;
    if (w >= E) return;

    long long s, d;
    if (g_is64) {
        const long long* p = (const long long*)ei_raw;
        s = p[w]; d = p[E + w];
    } else {
        const int* p = (const int*)ei_raw;
        s = p[w]; d = p[E + w];
    }

    float4 xv = *(const float4*)&g_x[s * DOUT + lane * 4];
    red_add_v4(&g_xs[d * DOUT + lane * 4], xv);

    if (lane < 4) {
        float4 av = *(const float4*)&eattr[(long long)w * EDIM + lane * 4];
        red_add_v4(&g_ea[d * EDIM + lane * 4], av);
    } else if (lane == 4) {
        atomicAdd(&g_deg[d], 1.0f);
    }
}

// ---------------- K3: combine (edge-linear + relu + residual) + BN stats ----
// 128 threads = one output col each; 64 nodes per block.
__global__ __launch_bounds__(128)
void k3_combine(const float* __restrict__ We, const float* __restrict__ be, int N)
{
    const int c  = threadIdx.x;
    const int n0 = blockIdx.x * 64;

    float w[EDIM];
    #pragma unroll
    for (int j = 0; j < EDIM; j++) w[j] = We[c * EDIM + j];
    const float bc = be[c];

    float s = 0.f, s2 = 0.f;
    for (int i = 0; i < 64; i++) {
        int n = n0 + i;
        if (n >= N) break;
        float elin = bc * g_deg[n];
        #pragma unroll
        for (int j = 0; j < EDIM; j++) elin += w[j] * g_ea[n * EDIM + j];
        float a = g_xs[n * DOUT + c] + elin;
        float h = fmaxf(a, 0.f) + g_res[n * DOUT + c];
        g_h[n * DOUT + c] = h;
        s += h; s2 += h * h;
    }
    atomicAdd(&g_sum[c],   s);
    atomicAdd(&g_sumsq[c], s2);
}

// ---------------- K4: finalize BN stats --------------------------------------
__global__ void k4_stats(const float* __restrict__ gamma,
                         const float* __restrict__ beta, int N)
{
    int c = threadIdx.x;
    float invN = 1.f / (float)N;
    float mean = g_sum[c] * invN;
    float var  = g_sumsq[c] * invN - mean * mean;
    float rstd = rsqrtf(var + BN_EPS);
    float sc   = gamma[c] * rstd;
    g_scale[c] = sc;
    g_shift[c] = beta[c] - mean * sc;
}

// ---------------- K5: normalize ----------------------------------------------
__global__ __launch_bounds__(256)
void k5_norm(float* __restrict__ out, int total4)
{
    int idx = blockIdx.x * blockDim.x + threadIdx.x;
    if (idx >= total4) return;
    int c4 = (idx & (DOUT / 4 - 1)) * 4;
    float4 h  = *(const float4*)&g_h[idx * 4];
    float4 sc = *(const float4*)&g_scale[c4];
    float4 sh = *(const float4*)&g_shift[c4];
    float4 o;
    o.x = h.x * sc.x + sh.x;
    o.y = h.y * sc.y + sh.y;
    o.z = h.z * sc.z + sh.z;
    o.w = h.w * sc.w + sh.w;
    ((float4*)out)[idx] = o;
}

// ---------------- launch ------------------------------------------------------
extern "C" void kernel_launch(void* const* d_in, const int* in_sizes, int n_in,
                              void* d_out, int out_size)
{
    const float* feats = (const float*)d_in[0];
    const void*  ei    = d_in[1];
    const float* eattr = (const float*)d_in[2];
    const float* Wrel  = (const float*)d_in[3];
    const float* brel  = (const float*)d_in[4];
    const float* We    = (const float*)d_in[5];
    const float* be    = (const float*)d_in[6];
    const float* Wres  = (const float*)d_in[7];
    const float* bres  = (const float*)d_in[8];
    const float* gamma = (const float*)d_in[9];
    const float* beta  = (const float*)d_in[10];

    const int N = in_sizes[0] / DIN;
    const int E = in_sizes[2] / EDIM;

    k0_detect<<<1, 256>>>((const unsigned int*)ei);
    k1_node_gemm<<<(N + 63) / 64, 256>>>(feats, Wrel, brel, Wres, bres, N);
    k2_edge<<<(E * 32 + 255) / 256, 256>>>(ei, eattr, E);
    k3_combine<<<(N + 63) / 64, 128>>>(We, be, N);
    k4_stats<<<1, 128>>>(gamma, beta, N);
    int total4 = N * DOUT / 4;
    k5_norm<<<(total4 + 255) / 256, 256>>>((float*)d_out, total4);
}